// round 11
// baseline (speedup 1.0000x reference)
#include <cuda_runtime.h>
#include <cuda_bf16.h>
#include <cstdint>

// ---------------------------------------------------------------------------
// InteractionGNN on GB300 — round 11: persistent edge kernels (weights fully
// resident in smem, 1 CTA/SM x 512 thr, ~63 tiles per CTA) + R10 node kernels
// and fused en+pe kernel unchanged.
// GEMM core: mma.sync bf16 3-term split (Ah*Wh + Ah*Wl + Al*Wh), fp32 accum.
// ---------------------------------------------------------------------------

#define N_NODES 100000
#define N_EDGES 600000
#define DD      128
#define NUM_ITERS 4

// ---------------- device scratch -------------------------------------------
__device__ float g_h  [(size_t)N_NODES * DD];
__device__ float g_h2 [(size_t)N_NODES * DD];
__device__ float g_m0 [(size_t)N_NODES * DD];
__device__ float g_m1 [(size_t)N_NODES * DD];
__device__ float g_e  [(size_t)N_EDGES * DD];
__device__ float g_pa [(size_t)N_NODES * DD];
__device__ float g_pb [(size_t)N_NODES * DD];
__device__ float g_pc [(size_t)N_NODES * DD];
__device__ float g_pd [(size_t)N_NODES * DD];
__device__ int   g_start[N_EDGES];
__device__ int   g_end  [N_EDGES];
// prepacked weights: 15 chunks x [128 n][128 k] bf16, hi and lo images
__device__ __nv_bfloat16 g_pwh[15 * 16384];
__device__ __nv_bfloat16 g_pwl[15 * 16384];

// ---------------- smem layouts ----------------------------------------------
static constexpr int ROW_B  = 272;
// streaming layout (node kernels + en_pe)
static constexpr int SM_B1  = 64;
static constexpr int SM_W2V = 576;
static constexpr int SM_B2  = 1088;
static constexpr int SM_B1P = 1600;
static constexpr int SM_IA  = 2112;
static constexpr int SM_IB  = 2368;
static constexpr int SM_AH  = 2688;
static constexpr int TBUF   = 64 * ROW_B;          // 17408
static constexpr int SM_AL  = SM_AH + TBUF;
static constexpr int SM_BH  = SM_AL + TBUF;
static constexpr int BBUF   = 128 * ROW_B;         // 34816
static constexpr int SM_BL  = SM_BH + BBUF;
static constexpr int SM_TOTAL = SM_BL + BBUF;      // 124160? (computed below ok)
// persistent layout (edge kernels)
static constexpr int P_B1  = 64;
static constexpr int P_B2  = 576;
static constexpr int P_IA  = 1088;
static constexpr int P_IB  = 1344;
static constexpr int P_AH  = 1600;
static constexpr int P_AL  = P_AH + TBUF;          // 19008
static constexpr int P_W1H = P_AL + TBUF;          // 36416
static constexpr int P_W1L = P_W1H + BBUF;         // 71232
static constexpr int P_W2H = P_W1L + BBUF;         // 106048
static constexpr int P_W2L = P_W2H + BBUF;         // 140864
static constexpr int P_WS  = P_W2L + BBUF;         // 175680 (scatter staging)
static constexpr int P_TOTAL = P_WS + BBUF;        // 210496

// ---------------- helpers -----------------------------------------------------
__device__ __forceinline__ uint32_t smem_u32(const void* p) {
    uint32_t a;
    asm("{ .reg .u64 t; cvta.to.shared.u64 t, %1; cvt.u32.u64 %0, t; }"
        : "=r"(a) : "l"(p));
    return a;
}

#define LDSM_X4(R0, R1, R2, R3, ADDR) \
    asm volatile("ldmatrix.sync.aligned.m8n8.x4.shared.b16 {%0,%1,%2,%3}, [%4];" \
                 : "=r"(R0), "=r"(R1), "=r"(R2), "=r"(R3) : "r"(ADDR))

__device__ __forceinline__ void mma16816(float* c, const uint32_t* a,
                                         const uint32_t* b) {
    asm volatile(
        "mma.sync.aligned.m16n8k16.row.col.f32.bf16.bf16.f32 "
        "{%0,%1,%2,%3}, {%4,%5,%6,%7}, {%8,%9}, {%0,%1,%2,%3};"
        : "+f"(c[0]), "+f"(c[1]), "+f"(c[2]), "+f"(c[3])
        : "r"(a[0]), "r"(a[1]), "r"(a[2]), "r"(a[3]), "r"(b[0]), "r"(b[1]));
}

__device__ __forceinline__ uint32_t pack_bf2(float a, float b) {
    __nv_bfloat162 t = __floats2bfloat162_rn(a, b);
    return *reinterpret_cast<uint32_t*>(&t);
}

__device__ __forceinline__ void split2(float x, float y, uint32_t& H, uint32_t& L) {
    __nv_bfloat16 hx = __float2bfloat16(x);
    __nv_bfloat16 hy = __float2bfloat16(y);
    float lx = x - __bfloat162float(hx);
    float ly = y - __bfloat162float(hy);
    H = pack_bf2(__bfloat162float(hx), __bfloat162float(hy));
    L = pack_bf2(lx, ly);
}

#define CP_WAIT_ALL() asm volatile("cp.async.wait_group 0;" ::: "memory")

// ======================= streaming-path helpers (R10) =======================
__device__ __forceinline__ void copyw_half(uint32_t sb, int tid, int chunk,
                                           int half) {
    const char* srcH = (const char*)(g_pwh + (size_t)chunk * 16384 + half * 8192);
    const char* srcL = (const char*)(g_pwl + (size_t)chunk * 16384 + half * 8192);
    #pragma unroll
    for (int i = tid; i < 1024; i += 256) {
        int rr = i >> 4, q = i & 15;
        uint32_t d = sb + SM_BH + rr * ROW_B + q * 16;
        asm volatile("cp.async.cg.shared.global [%0], [%1], 16;"
                     :: "r"(d), "l"(srcH + i * 16));
        asm volatile("cp.async.cg.shared.global [%0], [%1], 16;"
                     :: "r"(d + (uint32_t)(SM_BL - SM_BH)), "l"(srcL + i * 16));
    }
    asm volatile("cp.async.commit_group;" ::: "memory");
}

template <int KSTEPS>
__device__ __forceinline__ void gemm3h(uint32_t sb, int m0, int nloc,
                                       int a_ro, int a_co, int b_ro, int b_co,
                                       float accp[4][4]) {
    #pragma unroll
    for (int ks = 0; ks < KSTEPS; ++ks) {
        const int k0 = ks * 16;
        uint32_t ah[4], al[4];
        {
            uint32_t ro = (uint32_t)(m0 + a_ro) * ROW_B + (uint32_t)(k0 + a_co) * 2;
            LDSM_X4(ah[0], ah[1], ah[2], ah[3], sb + SM_AH + ro);
            LDSM_X4(al[0], al[1], al[2], al[3], sb + SM_AL + ro);
        }
        uint32_t bh[4][2], bl[4][2];
        #pragma unroll
        for (int nb = 0; nb < 2; ++nb) {
            uint32_t ro = (uint32_t)(nloc + nb * 16 + b_ro) * ROW_B +
                          (uint32_t)(k0 + b_co) * 2;
            uint32_t r0, r1, r2, r3;
            LDSM_X4(r0, r1, r2, r3, sb + SM_BH + ro);
            bh[nb * 2][0] = r0; bh[nb * 2][1] = r1;
            bh[nb * 2 + 1][0] = r2; bh[nb * 2 + 1][1] = r3;
            LDSM_X4(r0, r1, r2, r3, sb + SM_BL + ro);
            bl[nb * 2][0] = r0; bl[nb * 2][1] = r1;
            bl[nb * 2 + 1][0] = r2; bl[nb * 2 + 1][1] = r3;
        }
        #pragma unroll
        for (int na = 0; na < 4; ++na) {
            mma16816(accp[na], ah, bh[na]);
            mma16816(accp[na], ah, bl[na]);
            mma16816(accp[na], al, bh[na]);
        }
    }
}

template <int KS>
__device__ __forceinline__ void layer_gemm_issued(uint32_t sb, int tid, int chunk,
                                                  int m0, int nloc,
                                                  int a_ro, int a_co,
                                                  int b_ro, int b_co,
                                                  float acc[2][4][4]) {
    CP_WAIT_ALL();
    __syncthreads();
    gemm3h<KS>(sb, m0, nloc, a_ro, a_co, b_ro, b_co, acc[0]);
    __syncthreads();
    copyw_half(sb, tid, chunk, 1);
    CP_WAIT_ALL();
    __syncthreads();
    gemm3h<KS>(sb, m0, nloc, a_ro, a_co, b_ro, b_co, acc[1]);
}

__device__ __forceinline__ void zacc2(float acc[2][4][4]) {
    #pragma unroll
    for (int q = 0; q < 32; ++q) (&acc[0][0][0])[q] = 0.f;
}

template <int SRC_K>
__device__ __forceinline__ void stage_a(char* smem, int wid, int lane, int row0,
                                        const float* __restrict__ src, int nrows) {
    for (int r = wid; r < 64; r += 8) {
        int grow = row0 + r;
        float4 v = make_float4(0.f, 0.f, 0.f, 0.f);
        if (grow < nrows && lane < SRC_K / 4)
            v = ((const float4*)(src + (size_t)grow * SRC_K))[lane];
        if (lane < SRC_K / 4) {
            uint32_t h0, l0, h1, l1;
            split2(v.x, v.y, h0, l0);
            split2(v.z, v.w, h1, l1);
            uint32_t off = r * ROW_B + lane * 8;
            *(uint2*)(smem + SM_AH + off) = make_uint2(h0, h1);
            *(uint2*)(smem + SM_AL + off) = make_uint2(l0, l1);
        }
    }
}

__device__ __forceinline__ void acc_to_A(char* smem, float acc[2][4][4],
                                         int m0, int nwn, int g, int tig,
                                         const float* b1s, bool relu) {
    const int rl = m0 + g;
    #pragma unroll
    for (int p = 0; p < 2; ++p)
        #pragma unroll
        for (int na = 0; na < 4; ++na) {
            int cc = p * 64 + nwn + na * 8 + 2 * tig;
            float bx = b1s ? b1s[cc] : 0.f;
            float by = b1s ? b1s[cc + 1] : 0.f;
            float v0 = acc[p][na][0] + bx, v1 = acc[p][na][1] + by;
            float v2 = acc[p][na][2] + bx, v3 = acc[p][na][3] + by;
            if (relu) {
                v0 = fmaxf(v0, 0.f); v1 = fmaxf(v1, 0.f);
                v2 = fmaxf(v2, 0.f); v3 = fmaxf(v3, 0.f);
            }
            uint32_t H, L;
            split2(v0, v1, H, L);
            *(uint32_t*)(smem + SM_AH + rl * ROW_B + cc * 2) = H;
            *(uint32_t*)(smem + SM_AL + rl * ROW_B + cc * 2) = L;
            split2(v2, v3, H, L);
            *(uint32_t*)(smem + SM_AH + (rl + 8) * ROW_B + cc * 2) = H;
            *(uint32_t*)(smem + SM_AL + (rl + 8) * ROW_B + cc * 2) = L;
        }
}

__device__ __forceinline__ void acc_store(float* __restrict__ out,
                                          float acc[2][4][4], int row0,
                                          int m0, int nwn, int g, int tig,
                                          int nrows) {
    const int rl = m0 + g;
    const int g0 = row0 + rl, g1 = g0 + 8;
    #pragma unroll
    for (int p = 0; p < 2; ++p)
        #pragma unroll
        for (int na = 0; na < 4; ++na) {
            int cc = p * 64 + nwn + na * 8 + 2 * tig;
            if (g0 < nrows)
                *(float2*)(out + (size_t)g0 * DD + cc) =
                    make_float2(acc[p][na][0], acc[p][na][1]);
            if (g1 < nrows)
                *(float2*)(out + (size_t)g1 * DD + cc) =
                    make_float2(acc[p][na][2], acc[p][na][3]);
        }
}

__device__ __forceinline__ void pre_add(float acc[2][4][4],
                                        const float* __restrict__ U,
                                        const float* __restrict__ V,
                                        const int* s_ia, const int* s_ib,
                                        int row0, int m0, int nwn, int g,
                                        int tig, int nrows) {
    const int rl = m0 + g;
    #pragma unroll
    for (int half = 0; half < 2; ++half) {
        int rloc = rl + half * 8;
        int grow = row0 + rloc;
        if (grow < nrows) {
            const float* pu = U + (size_t)s_ia[rloc] * DD;
            const float* pv = V + (size_t)s_ib[rloc] * DD;
            #pragma unroll
            for (int p = 0; p < 2; ++p)
                #pragma unroll
                for (int na = 0; na < 4; ++na) {
                    int cc = p * 64 + nwn + na * 8 + 2 * tig;
                    float2 va = *(const float2*)(pu + cc);
                    float2 vb = *(const float2*)(pv + cc);
                    acc[p][na][half * 2 + 0] += va.x + vb.x;
                    acc[p][na][half * 2 + 1] += va.y + vb.y;
                }
        }
    }
}

// ======================= persistent-path helpers ============================
// copy a full weight chunk into resident buffers (512 threads)
__device__ __forceinline__ void copyw_full_p(uint32_t sb, int tid, int chunk,
                                             uint32_t dH, uint32_t dL) {
    const char* srcH = (const char*)(g_pwh + (size_t)chunk * 16384);
    const char* srcL = (const char*)(g_pwl + (size_t)chunk * 16384);
    #pragma unroll
    for (int i = tid; i < 2048; i += 512) {
        int rr = i >> 4, q = i & 15;
        uint32_t off = rr * ROW_B + q * 16;
        asm volatile("cp.async.cg.shared.global [%0], [%1], 16;"
                     :: "r"(sb + dH + off), "l"(srcH + i * 16));
        asm volatile("cp.async.cg.shared.global [%0], [%1], 16;"
                     :: "r"(sb + dL + off), "l"(srcL + i * 16));
    }
    asm volatile("cp.async.commit_group;" ::: "memory");
}

// full-K 3-term GEMM vs resident weights; warp tile 16(M) x 32(N)
__device__ __forceinline__ void gemm_full_p(uint32_t sb, uint32_t wH, uint32_t wL,
                                            int m0, int nwn,
                                            int a_ro, int a_co, int b_ro, int b_co,
                                            float acc[4][4]) {
    #pragma unroll
    for (int ks = 0; ks < 8; ++ks) {
        const int k0 = ks * 16;
        uint32_t ah[4], al[4];
        {
            uint32_t ro = (uint32_t)(m0 + a_ro) * ROW_B + (uint32_t)(k0 + a_co) * 2;
            LDSM_X4(ah[0], ah[1], ah[2], ah[3], sb + P_AH + ro);
            LDSM_X4(al[0], al[1], al[2], al[3], sb + P_AL + ro);
        }
        uint32_t bh[4][2], bl[4][2];
        #pragma unroll
        for (int nb = 0; nb < 2; ++nb) {
            uint32_t ro = (uint32_t)(nwn + nb * 16 + b_ro) * ROW_B +
                          (uint32_t)(k0 + b_co) * 2;
            uint32_t r0, r1, r2, r3;
            LDSM_X4(r0, r1, r2, r3, sb + wH + ro);
            bh[nb * 2][0] = r0; bh[nb * 2][1] = r1;
            bh[nb * 2 + 1][0] = r2; bh[nb * 2 + 1][1] = r3;
            LDSM_X4(r0, r1, r2, r3, sb + wL + ro);
            bl[nb * 2][0] = r0; bl[nb * 2][1] = r1;
            bl[nb * 2 + 1][0] = r2; bl[nb * 2 + 1][1] = r3;
        }
        #pragma unroll
        for (int na = 0; na < 4; ++na) {
            mma16816(acc[na], ah, bh[na]);
            mma16816(acc[na], ah, bl[na]);
            mma16816(acc[na], al, bh[na]);
        }
    }
}

// stage 64 rows x 128 fp32 (16 warps) into persistent A tiles; exact tiles only
__device__ __forceinline__ void stage_a_p(char* smem, int wid, int lane, int row0,
                                          const float* __restrict__ src) {
    #pragma unroll
    for (int r = wid; r < 64; r += 16) {
        float4 v = ((const float4*)(src + (size_t)(row0 + r) * DD))[lane];
        uint32_t h0, l0, h1, l1;
        split2(v.x, v.y, h0, l0);
        split2(v.z, v.w, h1, l1);
        uint32_t off = r * ROW_B + lane * 8;
        *(uint2*)(smem + P_AH + off) = make_uint2(h0, h1);
        *(uint2*)(smem + P_AL + off) = make_uint2(l0, l1);
    }
}

__device__ __forceinline__ void acc_to_A_p(char* smem, float acc[4][4],
                                           int m0, int nwn, int g, int tig,
                                           const float* b1s) {
    const int rl = m0 + g;
    #pragma unroll
    for (int na = 0; na < 4; ++na) {
        int cc = nwn + na * 8 + 2 * tig;
        float bx = b1s[cc], by = b1s[cc + 1];
        float v0 = fmaxf(acc[na][0] + bx, 0.f);
        float v1 = fmaxf(acc[na][1] + by, 0.f);
        float v2 = fmaxf(acc[na][2] + bx, 0.f);
        float v3 = fmaxf(acc[na][3] + by, 0.f);
        uint32_t H, L;
        split2(v0, v1, H, L);
        *(uint32_t*)(smem + P_AH + rl * ROW_B + cc * 2) = H;
        *(uint32_t*)(smem + P_AL + rl * ROW_B + cc * 2) = L;
        split2(v2, v3, H, L);
        *(uint32_t*)(smem + P_AH + (rl + 8) * ROW_B + cc * 2) = H;
        *(uint32_t*)(smem + P_AL + (rl + 8) * ROW_B + cc * 2) = L;
    }
}

__device__ __forceinline__ void pre_add_p(float acc[4][4],
                                          const float* __restrict__ U,
                                          const float* __restrict__ V,
                                          const int* s_ia, const int* s_ib,
                                          int m0, int nwn, int g, int tig) {
    const int rl = m0 + g;
    #pragma unroll
    for (int half = 0; half < 2; ++half) {
        int rloc = rl + half * 8;
        const float* pu = U + (size_t)s_ia[rloc] * DD;
        const float* pv = V + (size_t)s_ib[rloc] * DD;
        #pragma unroll
        for (int na = 0; na < 4; ++na) {
            int cc = nwn + na * 8 + 2 * tig;
            float2 va = *(const float2*)(pu + cc);
            float2 vb = *(const float2*)(pv + cc);
            acc[na][half * 2 + 0] += va.x + vb.x;
            acc[na][half * 2 + 1] += va.y + vb.y;
        }
    }
}

// ---------------- small utility kernels ------------------------------------
__global__ void convert_idx_kernel(const void* __restrict__ raw,
                                   int* __restrict__ st, int* __restrict__ en,
                                   int E) {
    __shared__ int s_is64;
    if (threadIdx.x == 0) {
        const unsigned int* w = (const unsigned int*)raw;
        unsigned int acc = 0;
        #pragma unroll 8
        for (int i = 0; i < 128; ++i) acc |= w[2 * i + 1];
        s_is64 = (acc == 0u);
    }
    __syncthreads();
    const int is64 = s_is64;
    int i = blockIdx.x * blockDim.x + threadIdx.x;
    if (i >= 2 * E) return;
    int v;
    if (is64) v = (int)((const long long*)raw)[i];
    else      v = ((const int*)raw)[i];
    if (i < E) st[i] = v; else en[i - E] = v;
}

__global__ void pack_w_kernel(const float* neW1, const float* neW2,
                              const float* eeW1, const float* eeW2,
                              const float* nnW1, const float* nnW2,
                              const float* enW1, const float* enW2,
                              const float* peW1,
                              __nv_bfloat16* gh, __nv_bfloat16* gl) {
    int t = blockIdx.x * blockDim.x + threadIdx.x;
    if (t >= 15 * 16384) return;
    int chunk = t >> 14;
    int e = t & 16383;
    int k = e & 127;
    int n = e >> 7;
    const float* W; int koff = 0; int kvalid = 128;
    switch (chunk) {
        case 0:  W = neW1; kvalid = 16; break;
        case 1:  W = neW2; break;
        case 2: case 3:  W = eeW1; koff = (chunk - 2) * 128; break;
        case 4:  W = eeW2; break;
        case 5: case 6:  W = nnW1; koff = (chunk - 5) * 128; break;
        case 7:  W = nnW2; break;
        case 8: case 9: case 10: W = enW1; koff = (chunk - 8) * 128; break;
        case 11: W = enW2; break;
        default: W = peW1; koff = (chunk - 12) * 128; break;
    }
    float x = (k < kvalid) ? W[(size_t)(koff + k) * 128 + n] : 0.f;
    __nv_bfloat16 h = __float2bfloat16(x);
    __nv_bfloat16 l = __float2bfloat16(x - __bfloat162float(h));
    gh[(size_t)chunk * 16384 + n * 128 + k] = h;
    gl[(size_t)chunk * 16384 + n * 128 + k] = l;
}

// ---------------------------------------------------------------------------
// Fused node kernel (streaming path, unchanged from R10).
// ---------------------------------------------------------------------------
template <int NCH, int KS1, bool PRE2, bool POST2, bool RES>
__global__ void __launch_bounds__(256, 3)
node_fused(const float* __restrict__ s0, const float* __restrict__ s1,
           int wqa, int wqb, float* __restrict__ Qa, float* __restrict__ Qb,
           int w1c0, int w2c,
           int wra, int wrb, float* __restrict__ Ra, float* __restrict__ Rb,
           const float* __restrict__ b1, const float* __restrict__ b2,
           const float* __restrict__ res, float* __restrict__ out,
           float* __restrict__ zrow, int nrows) {
    extern __shared__ char smem[];
    const uint32_t sb = smem_u32(smem);
    const int tid = threadIdx.x, lane = tid & 31, wid = tid >> 5;
    const int row0 = blockIdx.x * 64;
    const int g = lane >> 2, tig = lane & 3;
    const int m0 = (wid >> 1) * 16;
    const int nwn = (wid & 1) * 32;
    const int a_ro = (lane & 7) + ((lane >> 3) & 1) * 8;
    const int a_co = ((lane >> 4) & 1) * 8;
    const int b_ro = (lane & 7) + ((lane >> 4) & 1) * 8;
    const int b_co = ((lane >> 3) & 1) * 8;

    float* b1s = (float*)(smem + SM_B1);
    float* b2s = (float*)(smem + SM_B2);
    if (tid < 128) { b1s[tid] = b1[tid]; b2s[tid] = b2[tid]; }

    copyw_half(sb, tid, PRE2 ? wqa : w1c0, 0);

    if (zrow != nullptr) {
        float4* zp = (float4*)(zrow + (size_t)row0 * DD);
        int nz = (nrows - row0 < 64 ? nrows - row0 : 64) * 32;
        for (int i = tid; i < nz; i += 256)
            zp[i] = make_float4(0.f, 0.f, 0.f, 0.f);
    }

    stage_a<KS1 * 16>(smem, wid, lane, row0, s0, nrows);

    float acc[2][4][4];

    if constexpr (PRE2) {
        zacc2(acc);
        layer_gemm_issued<KS1>(sb, tid, wqa, m0, nwn, a_ro, a_co, b_ro, b_co, acc);
        __syncthreads();
        copyw_half(sb, tid, wqb, 0);
        acc_store(Qa, acc, row0, m0, nwn, g, tig, nrows);
        zacc2(acc);
        layer_gemm_issued<KS1>(sb, tid, wqb, m0, nwn, a_ro, a_co, b_ro, b_co, acc);
        __syncthreads();
        copyw_half(sb, tid, w1c0, 0);
        acc_store(Qb, acc, row0, m0, nwn, g, tig, nrows);
    }

    zacc2(acc);
    layer_gemm_issued<KS1>(sb, tid, w1c0, m0, nwn, a_ro, a_co, b_ro, b_co, acc);

    if constexpr (NCH == 2) {
        __syncthreads();
        copyw_half(sb, tid, w1c0 + 1, 0);
        stage_a<128>(smem, wid, lane, row0, s1, nrows);
        layer_gemm_issued<8>(sb, tid, w1c0 + 1, m0, nwn, a_ro, a_co, b_ro, b_co, acc);
    }

    __syncthreads();
    copyw_half(sb, tid, w2c, 0);
    acc_to_A(smem, acc, m0, nwn, g, tig, b1s, true);

    zacc2(acc);
    layer_gemm_issued<8>(sb, tid, w2c, m0, nwn, a_ro, a_co, b_ro, b_co, acc);

    {
        const int rl = m0 + g;
        #pragma unroll
        for (int half = 0; half < 2; ++half) {
            int grow = row0 + rl + half * 8;
            #pragma unroll
            for (int p = 0; p < 2; ++p)
                #pragma unroll
                for (int na = 0; na < 4; ++na) {
                    int cc = p * 64 + nwn + na * 8 + 2 * tig;
                    float bx = b2s[cc], by = b2s[cc + 1];
                    float rx = 0.f, ry = 0.f;
                    if (RES && grow < nrows) {
                        float2 rv = *(const float2*)(res + (size_t)grow * DD + cc);
                        rx = rv.x; ry = rv.y;
                    }
                    acc[p][na][half * 2 + 0] += bx + rx;
                    acc[p][na][half * 2 + 1] += by + ry;
                }
        }
    }

    if constexpr (POST2) {
        __syncthreads();
        copyw_half(sb, tid, wra, 0);
        acc_store(out, acc, row0, m0, nwn, g, tig, nrows);
        acc_to_A(smem, acc, m0, nwn, g, tig, nullptr, false);
        zacc2(acc);
        layer_gemm_issued<8>(sb, tid, wra, m0, nwn, a_ro, a_co, b_ro, b_co, acc);
        __syncthreads();
        copyw_half(sb, tid, wrb, 0);
        acc_store(Ra, acc, row0, m0, nwn, g, tig, nrows);
        zacc2(acc);
        layer_gemm_issued<8>(sb, tid, wrb, m0, nwn, a_ro, a_co, b_ro, b_co, acc);
        acc_store(Rb, acc, row0, m0, nwn, g, tig, nrows);
    } else {
        acc_store(out, acc, row0, m0, nwn, g, tig, nrows);
    }
}

// ---------------------------------------------------------------------------
// Persistent edge kernel.  1 CTA/SM x 512 thr (16 warps, 4Mx4N, tile 16x32).
// W1 (if NCH) and W2 fully resident in smem; loops over 64-edge tiles.
// NCH=0 (ee): layer1 = Pa/Pb gathers only.  RES: residual add of e.
// SCATTER: per-tile bulk-reduce rows into msgout[end].
// Assumes ntiles*64 == nrows (exact; true for N_EDGES).
// ---------------------------------------------------------------------------
template <int NCH, bool SCATTER, bool RES>
__global__ void __launch_bounds__(512, 1)
edge_persist(const float* __restrict__ e,
             const int* __restrict__ ip0, const int* __restrict__ ip1,
             const float* __restrict__ Pa, const float* __restrict__ Pb,
             int w1c, int w2c,
             const float* __restrict__ b1, const float* __restrict__ b2,
             float* __restrict__ out, float* __restrict__ msgout, int ntiles) {
    extern __shared__ char smem[];
    const uint32_t sb = smem_u32(smem);
    const int tid = threadIdx.x, lane = tid & 31, wid = tid >> 5;
    const int g = lane >> 2, tig = lane & 3;
    const int m0 = (wid >> 2) * 16;
    const int nwn = (wid & 3) * 32;
    const int a_ro = (lane & 7) + ((lane >> 3) & 1) * 8;
    const int a_co = ((lane >> 4) & 1) * 8;
    const int b_ro = (lane & 7) + ((lane >> 4) & 1) * 8;
    const int b_co = ((lane >> 3) & 1) * 8;

    float* b1s = (float*)(smem + P_B1);
    float* b2s = (float*)(smem + P_B2);
    int*   s_ia = (int*)(smem + P_IA);
    int*   s_ib = (int*)(smem + P_IB);

    if (tid < 128) { b1s[tid] = b1[tid]; b2s[tid] = b2[tid]; }
    if (NCH == 1) copyw_full_p(sb, tid, w1c, P_W1H, P_W1L);
    copyw_full_p(sb, tid, w2c, P_W2H, P_W2L);
    CP_WAIT_ALL();
    __syncthreads();

    for (int t = blockIdx.x; t < ntiles; t += gridDim.x) {
        const int row0 = t * 64;

        if (tid < 64) {
            int ia = ip0[row0 + tid], ib = ip1[row0 + tid];
            s_ia[tid] = ia; s_ib[tid] = ib;
            const char* pa = (const char*)(Pa + (size_t)ia * DD);
            const char* pb = (const char*)(Pb + (size_t)ib * DD);
            #pragma unroll
            for (int l = 0; l < 4; ++l) {
                asm volatile("prefetch.global.L2 [%0];" :: "l"(pa + l * 128));
                asm volatile("prefetch.global.L2 [%0];" :: "l"(pb + l * 128));
            }
        }

        float acc[4][4];
        #pragma unroll
        for (int q = 0; q < 16; ++q) (&acc[0][0])[q] = 0.f;

        if constexpr (NCH == 1) {
            stage_a_p(smem, wid, lane, row0, e);
            __syncthreads();                 // A + indices visible
            gemm_full_p(sb, P_W1H, P_W1L, m0, nwn, a_ro, a_co, b_ro, b_co, acc);
        } else {
            __syncthreads();                 // indices visible
        }

        pre_add_p(acc, Pa, Pb, s_ia, s_ib, m0, nwn, g, tig);
        __syncthreads();                     // layer-1 A reads done

        acc_to_A_p(smem, acc, m0, nwn, g, tig, b1s);
        __syncthreads();                     // hidden A visible

        #pragma unroll
        for (int q = 0; q < 16; ++q) (&acc[0][0])[q] = 0.f;
        gemm_full_p(sb, P_W2H, P_W2L, m0, nwn, a_ro, a_co, b_ro, b_co, acc);

        // epilogue: out = acc + b2 (+ e residual); stage into WS for scatter
        float* stg = (float*)(smem + P_WS);
        const int rl = m0 + g;
        #pragma unroll
        for (int half = 0; half < 2; ++half) {
            int rloc = rl + half * 8;
            int grow = row0 + rloc;
            #pragma unroll
            for (int na = 0; na < 4; ++na) {
                int cc = nwn + na * 8 + 2 * tig;
                float ox = acc[na][half * 2 + 0] + b2s[cc];
                float oy = acc[na][half * 2 + 1] + b2s[cc + 1];
                if (RES) {
                    float2 rv = *(const float2*)(e + (size_t)grow * DD + cc);
                    ox += rv.x; oy += rv.y;
                }
                float2 o = make_float2(ox, oy);
                *(float2*)(out + (size_t)grow * DD + cc) = o;
                if (SCATTER) *(float2*)(stg + rloc * DD + cc) = o;
            }
        }
        __syncthreads();                     // WS visible / A reads done

        if constexpr (SCATTER) {
            asm volatile("fence.proxy.async.shared::cta;" ::: "memory");
            if (tid < 64) {
                uint32_t src = sb + P_WS + tid * 512;
                float* dst = msgout + (size_t)s_ib[tid] * DD;
                asm volatile(
                    "cp.reduce.async.bulk.global.shared::cta.bulk_group.add.f32 "
                    "[%0], [%1], 512;"
                    :: "l"(dst), "r"(src) : "memory");
                asm volatile("cp.async.bulk.commit_group;" ::: "memory");
                asm volatile("cp.async.bulk.wait_group 0;" ::: "memory");
            }
        }
    }
}

// ---------------------------------------------------------------------------
// Fused final edge kernel (streaming path, unchanged from R10).
// ---------------------------------------------------------------------------
__global__ void __launch_bounds__(256, 3)
edge_en_pe(const float* __restrict__ e,
           const int* __restrict__ ip0, const int* __restrict__ ip1,
           const float* __restrict__ Qa, const float* __restrict__ Qb,
           const float* __restrict__ Ra, const float* __restrict__ Rb,
           const float* __restrict__ en_b1, const float* __restrict__ en_b2,
           const float* __restrict__ pe_b1v, const float* __restrict__ pe_b2v,
           const float* __restrict__ pe_w2v,
           float* __restrict__ pred, int nrows) {
    extern __shared__ char smem[];
    const uint32_t sb = smem_u32(smem);
    const int tid = threadIdx.x, lane = tid & 31, wid = tid >> 5;
    const int row0 = blockIdx.x * 64;
    const int g = lane >> 2, tig = lane & 3;
    const int m0 = (wid >> 1) * 16;
    const int nwn = (wid & 1) * 32;
    const int a_ro = (lane & 7) + ((lane >> 3) & 1) * 8;
    const int a_co = ((lane >> 4) & 1) * 8;
    const int b_ro = (lane & 7) + ((lane >> 4) & 1) * 8;
    const int b_co = ((lane >> 3) & 1) * 8;

    float* b1s = (float*)(smem + SM_B1);
    float* b2s = (float*)(smem + SM_B2);
    float* b1p = (float*)(smem + SM_B1P);
    float* w2s = (float*)(smem + SM_W2V);
    int*   s_ia = (int*)(smem + SM_IA);
    int*   s_ib = (int*)(smem + SM_IB);

    copyw_half(sb, tid, 10, 0);

    if (tid < 128) {
        b1s[tid] = en_b1[tid];
        b2s[tid] = en_b2[tid];
        b1p[tid] = pe_b1v[tid];
        w2s[tid] = pe_w2v[tid];
    }
    if (tid < 64) {
        int grow = row0 + tid;
        int ia = 0, ib = 0;
        if (grow < nrows) { ia = ip0[grow]; ib = ip1[grow]; }
        s_ia[tid] = ia; s_ib[tid] = ib;
        const char* qa = (const char*)(Qa + (size_t)ia * DD);
        const char* qb = (const char*)(Qb + (size_t)ib * DD);
        const char* ra = (const char*)(Ra + (size_t)ia * DD);
        const char* rb = (const char*)(Rb + (size_t)ib * DD);
        #pragma unroll
        for (int l = 0; l < 4; ++l) {
            asm volatile("prefetch.global.L2 [%0];" :: "l"(qa + l * 128));
            asm volatile("prefetch.global.L2 [%0];" :: "l"(qb + l * 128));
            asm volatile("prefetch.global.L2 [%0];" :: "l"(ra + l * 128));
            asm volatile("prefetch.global.L2 [%0];" :: "l"(rb + l * 128));
        }
    }

    float acc[2][4][4];
    zacc2(acc);

    stage_a<128>(smem, wid, lane, row0, e, nrows);
    layer_gemm_issued<8>(sb, tid, 10, m0, nwn, a_ro, a_co, b_ro, b_co, acc);
    pre_add(acc, Qa, Qb, s_ia, s_ib, row0, m0, nwn, g, tig, nrows);

    __syncthreads();
    copyw_half(sb, tid, 11, 0);
    acc_to_A(smem, acc, m0, nwn, g, tig, b1s, true);
    zacc2(acc);
    layer_gemm_issued<8>(sb, tid, 11, m0, nwn, a_ro, a_co, b_ro, b_co, acc);

    {
        const int rl = m0 + g;
        #pragma unroll
        for (int half = 0; half < 2; ++half) {
            int grow = row0 + rl + half * 8;
            if (grow < nrows) {
                #pragma unroll
                for (int p = 0; p < 2; ++p)
                    #pragma unroll
                    for (int na = 0; na < 4; ++na) {
                        int cc = p * 64 + nwn + na * 8 + 2 * tig;
                        float2 rv = *(const float2*)(e + (size_t)grow * DD + cc);
                        acc[p][na][half * 2 + 0] += b2s[cc] + rv.x;
                        acc[p][na][half * 2 + 1] += b2s[cc + 1] + rv.y;
                    }
            }
        }
    }

    __syncthreads();
    copyw_half(sb, tid, 14, 0);
    acc_to_A(smem, acc, m0, nwn, g, tig, nullptr, false);
    zacc2(acc);
    layer_gemm_issued<8>(sb, tid, 14, m0, nwn, a_ro, a_co, b_ro, b_co, acc);
    pre_add(acc, Ra, Rb, s_ia, s_ib, row0, m0, nwn, g, tig, nrows);

    float* hT = (float*)(smem + SM_AH);
    __syncthreads();
    {
        const int rl = m0 + g;
        #pragma unroll
        for (int p = 0; p < 2; ++p)
            #pragma unroll
            for (int na = 0; na < 4; ++na) {
                int cc = p * 64 + nwn + na * 8 + 2 * tig;
                hT[rl * 129 + cc]           = fmaxf(acc[p][na][0] + b1p[cc], 0.f);
                hT[rl * 129 + cc + 1]       = fmaxf(acc[p][na][1] + b1p[cc + 1], 0.f);
                hT[(rl + 8) * 129 + cc]     = fmaxf(acc[p][na][2] + b1p[cc], 0.f);
                hT[(rl + 8) * 129 + cc + 1] = fmaxf(acc[p][na][3] + b1p[cc + 1], 0.f);
            }
    }
    __syncthreads();
    if (tid < 64) {
        int grow = row0 + tid;
        float a = __ldg(&pe_b2v[0]);
        #pragma unroll 8
        for (int k = 0; k < 128; ++k) a += hT[tid * 129 + k] * w2s[k];
        if (grow < nrows) pred[grow] = a;
    }
}

// ---------------------------------------------------------------------------
extern "C" void kernel_launch(void* const* d_in, const int* in_sizes, int n_in,
                              void* d_out, int out_size) {
    const float* nodes = (const float*)d_in[0];
    const void*  eidx  = d_in[1];
    const float* ne_W1 = (const float*)d_in[2];
    const float* ne_b1 = (const float*)d_in[3];
    const float* ne_W2 = (const float*)d_in[4];
    const float* ne_b2 = (const float*)d_in[5];
    const float* ee_W1 = (const float*)d_in[6];
    const float* ee_b1 = (const float*)d_in[7];
    const float* ee_W2 = (const float*)d_in[8];
    const float* ee_b2 = (const float*)d_in[9];
    const float* nn_W1 = (const float*)d_in[10];
    const float* nn_b1 = (const float*)d_in[11];
    const float* nn_W2 = (const float*)d_in[12];
    const float* nn_b2 = (const float*)d_in[13];
    const float* en_W1 = (const float*)d_in[14];
    const float* en_b1 = (const float*)d_in[15];
    const float* en_W2 = (const float*)d_in[16];
    const float* en_b2 = (const float*)d_in[17];
    const float* pe_W1 = (const float*)d_in[18];
    const float* pe_b1 = (const float*)d_in[19];
    const float* pe_W2 = (const float*)d_in[20];
    const float* pe_b2 = (const float*)d_in[21];

    float *h, *h2, *m0, *m1, *e, *pa, *pb, *pc, *pd;
    int *st, *en_;
    __nv_bfloat16 *pwh, *pwl;
    cudaGetSymbolAddress((void**)&h,   g_h);
    cudaGetSymbolAddress((void**)&h2,  g_h2);
    cudaGetSymbolAddress((void**)&m0,  g_m0);
    cudaGetSymbolAddress((void**)&m1,  g_m1);
    cudaGetSymbolAddress((void**)&e,   g_e);
    cudaGetSymbolAddress((void**)&pa,  g_pa);
    cudaGetSymbolAddress((void**)&pb,  g_pb);
    cudaGetSymbolAddress((void**)&pc,  g_pc);
    cudaGetSymbolAddress((void**)&pd,  g_pd);
    cudaGetSymbolAddress((void**)&st,  g_start);
    cudaGetSymbolAddress((void**)&en_, g_end);
    cudaGetSymbolAddress((void**)&pwh, g_pwh);
    cudaGetSymbolAddress((void**)&pwl, g_pwl);

    cudaFuncSetAttribute(node_fused<1, 1, false, true, false>,
                         cudaFuncAttributeMaxDynamicSharedMemorySize, SM_TOTAL);
    cudaFuncSetAttribute(node_fused<2, 8, true, false, true>,
                         cudaFuncAttributeMaxDynamicSharedMemorySize, SM_TOTAL);
    cudaFuncSetAttribute(node_fused<2, 8, true, true, true>,
                         cudaFuncAttributeMaxDynamicSharedMemorySize, SM_TOTAL);
    cudaFuncSetAttribute(edge_persist<0, true, false>,
                         cudaFuncAttributeMaxDynamicSharedMemorySize, P_TOTAL);
    cudaFuncSetAttribute(edge_persist<1, true, true>,
                         cudaFuncAttributeMaxDynamicSharedMemorySize, P_TOTAL);
    cudaFuncSetAttribute(edge_en_pe,
                         cudaFuncAttributeMaxDynamicSharedMemorySize, SM_TOTAL);

    const int nblk_n = (N_NODES + 63) / 64;   // 1563
    const int nblk_e = (N_EDGES + 63) / 64;   // 9375
    const int ntile_e = N_EDGES / 64;         // 9375 (exact)
    const int PGRID = 148;

    convert_idx_kernel<<<(2 * N_EDGES + 255) / 256, 256>>>(eidx, st, en_, N_EDGES);
    pack_w_kernel<<<(15 * 16384 + 255) / 256, 256>>>(
        ne_W1, ne_W2, ee_W1, ee_W2, nn_W1, nn_W2, en_W1, en_W2, pe_W1, pwh, pwl);

    // h = MLP_ne(nodes);  Pa = h@eeW1a, Pb = h@eeW1b;  zero m0
    node_fused<1, 1, false, true, false><<<nblk_n, 256, SM_TOTAL>>>(
        nodes, nullptr, 0, 0, nullptr, nullptr, 0, 1,
        2, 3, pa, pb, ne_b1, ne_b2, nullptr, h, m0, N_NODES);

    // e = relu(Pa[s]+Pb[e]+b1)@eeW2 + b2;  scatter e -> m0   (persistent)
    edge_persist<0, true, false><<<PGRID, 512, P_TOTAL>>>(
        nullptr, st, en_, pa, pb, 0, 4,
        ee_b1, ee_b2, e, m0, ntile_e);

    float* hA = h;
    float* hB = h2;
    float* msgs[2] = {m0, m1};

    for (int it = 0; it < NUM_ITERS; ++it) {
        float* mcur = msgs[it & 1];
        float* mnxt = msgs[(it + 1) & 1];
        const bool last = (it == NUM_ITERS - 1);
        float* zr = last ? nullptr : mnxt;

        if (!last) {
            node_fused<2, 8, true, false, true><<<nblk_n, 256, SM_TOTAL>>>(
                hA, mcur, 8, 9, pa, pb, 5, 7,
                0, 0, nullptr, nullptr, nn_b1, nn_b2, hA, hB, zr, N_NODES);

            // e = (relu(e@enW1c + Qa[s]+Qb[e]+b1)@enW2 + b2) + e; scatter->mnxt
            edge_persist<1, true, true><<<PGRID, 512, P_TOTAL>>>(
                e, st, en_, pa, pb, 10, 11,
                en_b1, en_b2, e, mnxt, ntile_e);
        } else {
            node_fused<2, 8, true, true, true><<<nblk_n, 256, SM_TOTAL>>>(
                hA, mcur, 8, 9, pa, pb, 5, 7,
                12, 13, pc, pd, nn_b1, nn_b2, hA, hB, zr, N_NODES);

            edge_en_pe<<<nblk_e, 256, SM_TOTAL>>>(
                e, st, en_, pa, pb, pc, pd,
                en_b1, en_b2, pe_b1, pe_b2, pe_W2,
                (float*)d_out, N_EDGES);
        }

        float* t = hA; hA = hB; hB = t;
    }
}

// round 12
// speedup vs baseline: 1.1168x; 1.1168x over previous
#include <cuda_runtime.h>
#include <cuda_bf16.h>
#include <cstdint>

// ---------------------------------------------------------------------------
// InteractionGNN on GB300 — round 12: revert R11 persistent experiment (it
// regressed: 16 warps/SM lost more overlap than resident weights saved).
// Base = R10 (best, 3722us) + coalesced e-store via the scatter staging
// buffer (fragment stores scattered 8B -> staged smem -> 16B coalesced STG).
// GEMM core: mma.sync bf16 3-term split (Ah*Wh + Ah*Wl + Al*Wh), fp32 accum.
// ---------------------------------------------------------------------------

#define N_NODES 100000
#define N_EDGES 600000
#define DD      128
#define NUM_ITERS 4

// ---------------- device scratch -------------------------------------------
__device__ float g_h  [(size_t)N_NODES * DD];
__device__ float g_h2 [(size_t)N_NODES * DD];
__device__ float g_m0 [(size_t)N_NODES * DD];
__device__ float g_m1 [(size_t)N_NODES * DD];
__device__ float g_e  [(size_t)N_EDGES * DD];
__device__ float g_pa [(size_t)N_NODES * DD];
__device__ float g_pb [(size_t)N_NODES * DD];
__device__ float g_pc [(size_t)N_NODES * DD];
__device__ float g_pd [(size_t)N_NODES * DD];
__device__ int   g_start[N_EDGES];
__device__ int   g_end  [N_EDGES];
// prepacked weights: 15 chunks x [128 n][128 k] bf16, hi and lo images
__device__ __nv_bfloat16 g_pwh[15 * 16384];
__device__ __nv_bfloat16 g_pwl[15 * 16384];

// ---------------- smem layout ------------------------------------------------
static constexpr int ROW_B  = 272;
static constexpr int SM_B1  = 64;     // 128 f32
static constexpr int SM_W2V = 576;    // 128 f32
static constexpr int SM_B2  = 1088;   // 128 f32
static constexpr int SM_B1P = 1600;   // 128 f32 (pe_b1 in fused kernel)
static constexpr int SM_IA  = 2112;   // 64 ints
static constexpr int SM_IB  = 2368;   // 64 ints
static constexpr int SM_AH  = 2688;
static constexpr int TBUF   = 64 * ROW_B;          // 17408
static constexpr int SM_AL  = SM_AH + TBUF;        // 20096
static constexpr int SM_BH  = SM_AL + TBUF;        // 37504
static constexpr int SM_BL  = SM_BH + TBUF;        // 54912
static constexpr int SM_TOTAL = SM_BL + TBUF;      // 72320
// scatter staging: 64 rows x 512 B = 32768, overlaid on A tiles
static constexpr int SM_STG = SM_AH;

// ---------------- helpers -----------------------------------------------------
__device__ __forceinline__ uint32_t smem_u32(const void* p) {
    uint32_t a;
    asm("{ .reg .u64 t; cvta.to.shared.u64 t, %1; cvt.u32.u64 %0, t; }"
        : "=r"(a) : "l"(p));
    return a;
}

#define LDSM_X4(R0, R1, R2, R3, ADDR) \
    asm volatile("ldmatrix.sync.aligned.m8n8.x4.shared.b16 {%0,%1,%2,%3}, [%4];" \
                 : "=r"(R0), "=r"(R1), "=r"(R2), "=r"(R3) : "r"(ADDR))

__device__ __forceinline__ void mma16816(float* c, const uint32_t* a,
                                         const uint32_t* b) {
    asm volatile(
        "mma.sync.aligned.m16n8k16.row.col.f32.bf16.bf16.f32 "
        "{%0,%1,%2,%3}, {%4,%5,%6,%7}, {%8,%9}, {%0,%1,%2,%3};"
        : "+f"(c[0]), "+f"(c[1]), "+f"(c[2]), "+f"(c[3])
        : "r"(a[0]), "r"(a[1]), "r"(a[2]), "r"(a[3]), "r"(b[0]), "r"(b[1]));
}

__device__ __forceinline__ uint32_t pack_bf2(float a, float b) {
    __nv_bfloat162 t = __floats2bfloat162_rn(a, b);
    return *reinterpret_cast<uint32_t*>(&t);
}

__device__ __forceinline__ void split2(float x, float y, uint32_t& H, uint32_t& L) {
    __nv_bfloat16 hx = __float2bfloat16(x);
    __nv_bfloat16 hy = __float2bfloat16(y);
    float lx = x - __bfloat162float(hx);
    float ly = y - __bfloat162float(hy);
    H = pack_bf2(__bfloat162float(hx), __bfloat162float(hy));
    L = pack_bf2(lx, ly);
}

#define CP_WAIT_ALL() asm volatile("cp.async.wait_group 0;" ::: "memory")

// async copy of one 64-N-row half of a weight chunk into B hi/lo tiles.
__device__ __forceinline__ void copyw_half(uint32_t sb, int tid, int chunk,
                                           int half) {
    const char* srcH = (const char*)(g_pwh + (size_t)chunk * 16384 + half * 8192);
    const char* srcL = (const char*)(g_pwl + (size_t)chunk * 16384 + half * 8192);
    #pragma unroll
    for (int i = tid; i < 1024; i += 256) {
        int rr = i >> 4, q = i & 15;
        uint32_t d = sb + SM_BH + rr * ROW_B + q * 16;
        asm volatile("cp.async.cg.shared.global [%0], [%1], 16;"
                     :: "r"(d), "l"(srcH + i * 16));
        asm volatile("cp.async.cg.shared.global [%0], [%1], 16;"
                     :: "r"(d + (uint32_t)TBUF), "l"(srcL + i * 16));
    }
    asm volatile("cp.async.commit_group;" ::: "memory");
}

// 3-term split GEMM over one B half; warp tile 16(M) x 32(N-local)
template <int KSTEPS>
__device__ __forceinline__ void gemm3h(uint32_t sb, int m0, int nloc,
                                       int a_ro, int a_co, int b_ro, int b_co,
                                       float accp[4][4]) {
    #pragma unroll
    for (int ks = 0; ks < KSTEPS; ++ks) {
        const int k0 = ks * 16;
        uint32_t ah[4], al[4];
        {
            uint32_t ro = (uint32_t)(m0 + a_ro) * ROW_B + (uint32_t)(k0 + a_co) * 2;
            LDSM_X4(ah[0], ah[1], ah[2], ah[3], sb + SM_AH + ro);
            LDSM_X4(al[0], al[1], al[2], al[3], sb + SM_AL + ro);
        }
        uint32_t bh[4][2], bl[4][2];
        #pragma unroll
        for (int nb = 0; nb < 2; ++nb) {
            uint32_t ro = (uint32_t)(nloc + nb * 16 + b_ro) * ROW_B +
                          (uint32_t)(k0 + b_co) * 2;
            uint32_t r0, r1, r2, r3;
            LDSM_X4(r0, r1, r2, r3, sb + SM_BH + ro);
            bh[nb * 2][0] = r0; bh[nb * 2][1] = r1;
            bh[nb * 2 + 1][0] = r2; bh[nb * 2 + 1][1] = r3;
            LDSM_X4(r0, r1, r2, r3, sb + SM_BL + ro);
            bl[nb * 2][0] = r0; bl[nb * 2][1] = r1;
            bl[nb * 2 + 1][0] = r2; bl[nb * 2 + 1][1] = r3;
        }
        #pragma unroll
        for (int na = 0; na < 4; ++na) {
            mma16816(accp[na], ah, bh[na]);
            mma16816(accp[na], ah, bl[na]);
            mma16816(accp[na], al, bh[na]);
        }
    }
}

// Full layer GEMM assuming copyw_half(chunk, 0) was ALREADY issued by caller.
template <int KS>
__device__ __forceinline__ void layer_gemm_issued(uint32_t sb, int tid, int chunk,
                                                  int m0, int nloc,
                                                  int a_ro, int a_co,
                                                  int b_ro, int b_co,
                                                  float acc[2][4][4]) {
    CP_WAIT_ALL();
    __syncthreads();
    gemm3h<KS>(sb, m0, nloc, a_ro, a_co, b_ro, b_co, acc[0]);
    __syncthreads();
    copyw_half(sb, tid, chunk, 1);
    CP_WAIT_ALL();
    __syncthreads();
    gemm3h<KS>(sb, m0, nloc, a_ro, a_co, b_ro, b_co, acc[1]);
}

__device__ __forceinline__ void zacc2(float acc[2][4][4]) {
    #pragma unroll
    for (int q = 0; q < 32; ++q) (&acc[0][0][0])[q] = 0.f;
}

// stage 64 rows x SRC_K fp32 into A hi/lo smem tiles (contiguous rows)
template <int SRC_K>
__device__ __forceinline__ void stage_a(char* smem, int wid, int lane, int row0,
                                        const float* __restrict__ src, int nrows) {
    for (int r = wid; r < 64; r += 8) {
        int grow = row0 + r;
        float4 v = make_float4(0.f, 0.f, 0.f, 0.f);
        if (grow < nrows && lane < SRC_K / 4)
            v = ((const float4*)(src + (size_t)grow * SRC_K))[lane];
        if (lane < SRC_K / 4) {
            uint32_t h0, l0, h1, l1;
            split2(v.x, v.y, h0, l0);
            split2(v.z, v.w, h1, l1);
            uint32_t off = r * ROW_B + lane * 8;
            *(uint2*)(smem + SM_AH + off) = make_uint2(h0, h1);
            *(uint2*)(smem + SM_AL + off) = make_uint2(l0, l1);
        }
    }
}

// split acc (optional bias+relu) into A hi/lo tiles (cols = both N halves)
__device__ __forceinline__ void acc_to_A(char* smem, float acc[2][4][4],
                                         int m0, int nwn, int g, int tig,
                                         const float* b1s, bool relu) {
    const int rl = m0 + g;
    #pragma unroll
    for (int p = 0; p < 2; ++p)
        #pragma unroll
        for (int na = 0; na < 4; ++na) {
            int cc = p * 64 + nwn + na * 8 + 2 * tig;
            float bx = b1s ? b1s[cc] : 0.f;
            float by = b1s ? b1s[cc + 1] : 0.f;
            float v0 = acc[p][na][0] + bx, v1 = acc[p][na][1] + by;
            float v2 = acc[p][na][2] + bx, v3 = acc[p][na][3] + by;
            if (relu) {
                v0 = fmaxf(v0, 0.f); v1 = fmaxf(v1, 0.f);
                v2 = fmaxf(v2, 0.f); v3 = fmaxf(v3, 0.f);
            }
            uint32_t H, L;
            split2(v0, v1, H, L);
            *(uint32_t*)(smem + SM_AH + rl * ROW_B + cc * 2) = H;
            *(uint32_t*)(smem + SM_AL + rl * ROW_B + cc * 2) = L;
            split2(v2, v3, H, L);
            *(uint32_t*)(smem + SM_AH + (rl + 8) * ROW_B + cc * 2) = H;
            *(uint32_t*)(smem + SM_AL + (rl + 8) * ROW_B + cc * 2) = L;
        }
}

// raw store of acc to out[row][col]
__device__ __forceinline__ void acc_store(float* __restrict__ out,
                                          float acc[2][4][4], int row0,
                                          int m0, int nwn, int g, int tig,
                                          int nrows) {
    const int rl = m0 + g;
    const int g0 = row0 + rl, g1 = g0 + 8;
    #pragma unroll
    for (int p = 0; p < 2; ++p)
        #pragma unroll
        for (int na = 0; na < 4; ++na) {
            int cc = p * 64 + nwn + na * 8 + 2 * tig;
            if (g0 < nrows)
                *(float2*)(out + (size_t)g0 * DD + cc) =
                    make_float2(acc[p][na][0], acc[p][na][1]);
            if (g1 < nrows)
                *(float2*)(out + (size_t)g1 * DD + cc) =
                    make_float2(acc[p][na][2], acc[p][na][3]);
        }
}

// gather-add: acc += U[ia] + V[ib]  (per-row indices from smem)
__device__ __forceinline__ void pre_add(float acc[2][4][4],
                                        const float* __restrict__ U,
                                        const float* __restrict__ V,
                                        const int* s_ia, const int* s_ib,
                                        int row0, int m0, int nwn, int g,
                                        int tig, int nrows) {
    const int rl = m0 + g;
    #pragma unroll
    for (int half = 0; half < 2; ++half) {
        int rloc = rl + half * 8;
        int grow = row0 + rloc;
        if (grow < nrows) {
            const float* pu = U + (size_t)s_ia[rloc] * DD;
            const float* pv = V + (size_t)s_ib[rloc] * DD;
            #pragma unroll
            for (int p = 0; p < 2; ++p)
                #pragma unroll
                for (int na = 0; na < 4; ++na) {
                    int cc = p * 64 + nwn + na * 8 + 2 * tig;
                    float2 va = *(const float2*)(pu + cc);
                    float2 vb = *(const float2*)(pv + cc);
                    acc[p][na][half * 2 + 0] += va.x + vb.x;
                    acc[p][na][half * 2 + 1] += va.y + vb.y;
                }
        }
    }
}

// ---------------- small utility kernels ------------------------------------
__global__ void convert_idx_kernel(const void* __restrict__ raw,
                                   int* __restrict__ st, int* __restrict__ en,
                                   int E) {
    __shared__ int s_is64;
    if (threadIdx.x == 0) {
        const unsigned int* w = (const unsigned int*)raw;
        unsigned int acc = 0;
        #pragma unroll 8
        for (int i = 0; i < 128; ++i) acc |= w[2 * i + 1];
        s_is64 = (acc == 0u);
    }
    __syncthreads();
    const int is64 = s_is64;
    int i = blockIdx.x * blockDim.x + threadIdx.x;
    if (i >= 2 * E) return;
    int v;
    if (is64) v = (int)((const long long*)raw)[i];
    else      v = ((const int*)raw)[i];
    if (i < E) st[i] = v; else en[i - E] = v;
}

// Pack weights transposed: image[chunk][n][k] = W[(koff+k)*128 + n], bf16 hi/lo.
// 0:ne_W1(k<16) 1:ne_W2  2-3:ee_W1(a,b) 4:ee_W2  5-6:nn_W1 7:nn_W2
// 8-10:en_W1(a,b,c) 11:en_W2  12-14:pe_W1(a,b,c)
__global__ void pack_w_kernel(const float* neW1, const float* neW2,
                              const float* eeW1, const float* eeW2,
                              const float* nnW1, const float* nnW2,
                              const float* enW1, const float* enW2,
                              const float* peW1,
                              __nv_bfloat16* gh, __nv_bfloat16* gl) {
    int t = blockIdx.x * blockDim.x + threadIdx.x;
    if (t >= 15 * 16384) return;
    int chunk = t >> 14;
    int e = t & 16383;
    int k = e & 127;
    int n = e >> 7;
    const float* W; int koff = 0; int kvalid = 128;
    switch (chunk) {
        case 0:  W = neW1; kvalid = 16; break;
        case 1:  W = neW2; break;
        case 2: case 3:  W = eeW1; koff = (chunk - 2) * 128; break;
        case 4:  W = eeW2; break;
        case 5: case 6:  W = nnW1; koff = (chunk - 5) * 128; break;
        case 7:  W = nnW2; break;
        case 8: case 9: case 10: W = enW1; koff = (chunk - 8) * 128; break;
        case 11: W = enW2; break;
        default: W = peW1; koff = (chunk - 12) * 128; break;
    }
    float x = (k < kvalid) ? W[(size_t)(koff + k) * 128 + n] : 0.f;
    __nv_bfloat16 h = __float2bfloat16(x);
    __nv_bfloat16 l = __float2bfloat16(x - __bfloat162float(h));
    gh[(size_t)chunk * 16384 + n * 128 + k] = h;
    gl[(size_t)chunk * 16384 + n * 128 + k] = l;
}

// ---------------------------------------------------------------------------
// Fused node kernel.  64 rows/CTA, 256 thr, warp tile 16x32.
// ---------------------------------------------------------------------------
template <int NCH, int KS1, bool PRE2, bool POST2, bool RES>
__global__ void __launch_bounds__(256, 3)
node_fused(const float* __restrict__ s0, const float* __restrict__ s1,
           int wqa, int wqb, float* __restrict__ Qa, float* __restrict__ Qb,
           int w1c0, int w2c,
           int wra, int wrb, float* __restrict__ Ra, float* __restrict__ Rb,
           const float* __restrict__ b1, const float* __restrict__ b2,
           const float* __restrict__ res, float* __restrict__ out,
           float* __restrict__ zrow, int nrows) {
    extern __shared__ char smem[];
    const uint32_t sb = smem_u32(smem);
    const int tid = threadIdx.x, lane = tid & 31, wid = tid >> 5;
    const int row0 = blockIdx.x * 64;
    const int g = lane >> 2, tig = lane & 3;
    const int m0 = (wid >> 1) * 16;
    const int nwn = (wid & 1) * 32;
    const int a_ro = (lane & 7) + ((lane >> 3) & 1) * 8;
    const int a_co = ((lane >> 4) & 1) * 8;
    const int b_ro = (lane & 7) + ((lane >> 4) & 1) * 8;
    const int b_co = ((lane >> 3) & 1) * 8;

    float* b1s = (float*)(smem + SM_B1);
    float* b2s = (float*)(smem + SM_B2);
    if (tid < 128) { b1s[tid] = b1[tid]; b2s[tid] = b2[tid]; }

    copyw_half(sb, tid, PRE2 ? wqa : w1c0, 0);

    if (zrow != nullptr) {
        float4* zp = (float4*)(zrow + (size_t)row0 * DD);
        int nz = (nrows - row0 < 64 ? nrows - row0 : 64) * 32;
        for (int i = tid; i < nz; i += 256)
            zp[i] = make_float4(0.f, 0.f, 0.f, 0.f);
    }

    stage_a<KS1 * 16>(smem, wid, lane, row0, s0, nrows);

    float acc[2][4][4];

    if constexpr (PRE2) {
        zacc2(acc);
        layer_gemm_issued<KS1>(sb, tid, wqa, m0, nwn, a_ro, a_co, b_ro, b_co, acc);
        __syncthreads();
        copyw_half(sb, tid, wqb, 0);
        acc_store(Qa, acc, row0, m0, nwn, g, tig, nrows);
        zacc2(acc);
        layer_gemm_issued<KS1>(sb, tid, wqb, m0, nwn, a_ro, a_co, b_ro, b_co, acc);
        __syncthreads();
        copyw_half(sb, tid, w1c0, 0);
        acc_store(Qb, acc, row0, m0, nwn, g, tig, nrows);
    }

    zacc2(acc);
    layer_gemm_issued<KS1>(sb, tid, w1c0, m0, nwn, a_ro, a_co, b_ro, b_co, acc);

    if constexpr (NCH == 2) {
        __syncthreads();
        copyw_half(sb, tid, w1c0 + 1, 0);
        stage_a<128>(smem, wid, lane, row0, s1, nrows);
        layer_gemm_issued<8>(sb, tid, w1c0 + 1, m0, nwn, a_ro, a_co, b_ro, b_co, acc);
    }

    __syncthreads();
    copyw_half(sb, tid, w2c, 0);
    acc_to_A(smem, acc, m0, nwn, g, tig, b1s, true);

    zacc2(acc);
    layer_gemm_issued<8>(sb, tid, w2c, m0, nwn, a_ro, a_co, b_ro, b_co, acc);

    {
        const int rl = m0 + g;
        #pragma unroll
        for (int half = 0; half < 2; ++half) {
            int grow = row0 + rl + half * 8;
            #pragma unroll
            for (int p = 0; p < 2; ++p)
                #pragma unroll
                for (int na = 0; na < 4; ++na) {
                    int cc = p * 64 + nwn + na * 8 + 2 * tig;
                    float bx = b2s[cc], by = b2s[cc + 1];
                    float rx = 0.f, ry = 0.f;
                    if (RES && grow < nrows) {
                        float2 rv = *(const float2*)(res + (size_t)grow * DD + cc);
                        rx = rv.x; ry = rv.y;
                    }
                    acc[p][na][half * 2 + 0] += bx + rx;
                    acc[p][na][half * 2 + 1] += by + ry;
                }
        }
    }

    if constexpr (POST2) {
        __syncthreads();
        copyw_half(sb, tid, wra, 0);
        acc_store(out, acc, row0, m0, nwn, g, tig, nrows);
        acc_to_A(smem, acc, m0, nwn, g, tig, nullptr, false);
        zacc2(acc);
        layer_gemm_issued<8>(sb, tid, wra, m0, nwn, a_ro, a_co, b_ro, b_co, acc);
        __syncthreads();
        copyw_half(sb, tid, wrb, 0);
        acc_store(Ra, acc, row0, m0, nwn, g, tig, nrows);
        zacc2(acc);
        layer_gemm_issued<8>(sb, tid, wrb, m0, nwn, a_ro, a_co, b_ro, b_co, acc);
        acc_store(Rb, acc, row0, m0, nwn, g, tig, nrows);
    } else {
        acc_store(out, acc, row0, m0, nwn, g, tig, nrows);
    }
}

// ---------------------------------------------------------------------------
// Edge kernel.  64 edges/CTA, 256 thr, warp tile 16x32.
// SCATTER: fragments -> smem staging; coalesced 16B copy to out; then
// cp.reduce.async.bulk add into msgout[end].
// ---------------------------------------------------------------------------
template <int NCH, bool SCATTER, bool RES>
__global__ void __launch_bounds__(256, 3)
edge_mlp(const float* __restrict__ s0,
         const int* __restrict__ ip0, const int* __restrict__ ip1,
         const float* __restrict__ Pa, const float* __restrict__ Pb,
         int w1c, int w2c,
         const float* __restrict__ b1, const float* __restrict__ b2,
         const float* __restrict__ res, float* __restrict__ out,
         float* __restrict__ msgout, int nrows) {
    extern __shared__ char smem[];
    const uint32_t sb = smem_u32(smem);
    const int tid = threadIdx.x, lane = tid & 31, wid = tid >> 5;
    const int row0 = blockIdx.x * 64;
    const int g = lane >> 2, tig = lane & 3;
    const int m0 = (wid >> 1) * 16;
    const int nwn = (wid & 1) * 32;
    const int a_ro = (lane & 7) + ((lane >> 3) & 1) * 8;
    const int a_co = ((lane >> 4) & 1) * 8;
    const int b_ro = (lane & 7) + ((lane >> 4) & 1) * 8;
    const int b_co = ((lane >> 3) & 1) * 8;

    float* b1s = (float*)(smem + SM_B1);
    float* b2s = (float*)(smem + SM_B2);
    int*   s_ia = (int*)(smem + SM_IA);
    int*   s_ib = (int*)(smem + SM_IB);

    copyw_half(sb, tid, NCH == 1 ? w1c : w2c, 0);

    if (tid < 128) { b1s[tid] = b1[tid]; b2s[tid] = b2[tid]; }
    if (tid < 64) {
        int grow = row0 + tid;
        int ia = 0, ib = 0;
        if (grow < nrows) { ia = ip0[grow]; ib = ip1[grow]; }
        s_ia[tid] = ia; s_ib[tid] = ib;
        const char* pa = (const char*)(Pa + (size_t)ia * DD);
        const char* pb = (const char*)(Pb + (size_t)ib * DD);
        #pragma unroll
        for (int l = 0; l < 4; ++l) {
            asm volatile("prefetch.global.L2 [%0];" :: "l"(pa + l * 128));
            asm volatile("prefetch.global.L2 [%0];" :: "l"(pb + l * 128));
        }
    }

    float acc[2][4][4];
    zacc2(acc);

    if constexpr (NCH == 1) {
        stage_a<128>(smem, wid, lane, row0, s0, nrows);
        layer_gemm_issued<8>(sb, tid, w1c, m0, nwn, a_ro, a_co, b_ro, b_co, acc);
    } else {
        __syncthreads();
    }

    pre_add(acc, Pa, Pb, s_ia, s_ib, row0, m0, nwn, g, tig, nrows);

    if constexpr (NCH == 1) {
        __syncthreads();
        copyw_half(sb, tid, w2c, 0);
    }
    acc_to_A(smem, acc, m0, nwn, g, tig, b1s, true);
    zacc2(acc);
    layer_gemm_issued<8>(sb, tid, w2c, m0, nwn, a_ro, a_co, b_ro, b_co, acc);

    // epilogue
    if constexpr (!SCATTER) {
        const int rl = m0 + g;
        #pragma unroll
        for (int half = 0; half < 2; ++half) {
            int rloc = rl + half * 8;
            int grow = row0 + rloc;
            if (grow < nrows) {
                #pragma unroll
                for (int p = 0; p < 2; ++p)
                    #pragma unroll
                    for (int na = 0; na < 4; ++na) {
                        int cc = p * 64 + nwn + na * 8 + 2 * tig;
                        float ox = acc[p][na][half * 2 + 0] + b2s[cc];
                        float oy = acc[p][na][half * 2 + 1] + b2s[cc + 1];
                        if (RES) {
                            float2 rv = *(const float2*)(res + (size_t)grow * DD + cc);
                            ox += rv.x; oy += rv.y;
                        }
                        *(float2*)(out + (size_t)grow * DD + cc) = make_float2(ox, oy);
                    }
            }
        }
    } else {
        // fragments -> smem staging only (no scattered global stores)
        __syncthreads();      // all warps done reading A/B tiles
        float* stg = (float*)(smem + SM_STG);   // [64][128] fp32
        const int rl = m0 + g;
        #pragma unroll
        for (int half = 0; half < 2; ++half) {
            int rloc = rl + half * 8;
            int grow = row0 + rloc;
            if (grow < nrows) {
                #pragma unroll
                for (int p = 0; p < 2; ++p)
                    #pragma unroll
                    for (int na = 0; na < 4; ++na) {
                        int cc = p * 64 + nwn + na * 8 + 2 * tig;
                        float ox = acc[p][na][half * 2 + 0] + b2s[cc];
                        float oy = acc[p][na][half * 2 + 1] + b2s[cc + 1];
                        if (RES) {
                            float2 rv = *(const float2*)(res + (size_t)grow * DD + cc);
                            ox += rv.x; oy += rv.y;
                        }
                        *(float2*)(stg + rloc * DD + cc) = make_float2(ox, oy);
                    }
            }
        }
        __syncthreads();
        // coalesced 16B copy stg -> out (edge tiles are exact: nrows%64==0)
        {
            const int4* sp = (const int4*)stg;
            int4* op = (int4*)(out + (size_t)row0 * DD);
            #pragma unroll
            for (int i = tid; i < 2048; i += 256) op[i] = sp[i];
        }
        asm volatile("fence.proxy.async.shared::cta;" ::: "memory");
        if (tid < 64 && row0 + tid < nrows) {
            uint32_t src = sb + SM_STG + tid * 512;
            float* dst = msgout + (size_t)s_ib[tid] * DD;
            asm volatile(
                "cp.reduce.async.bulk.global.shared::cta.bulk_group.add.f32 "
                "[%0], [%1], 512;"
                :: "l"(dst), "r"(src) : "memory");
        }
        asm volatile("cp.async.bulk.commit_group;" ::: "memory");
        asm volatile("cp.async.bulk.wait_group 0;" ::: "memory");
    }
}

// ---------------------------------------------------------------------------
// Fused final edge kernel: e_new = en-MLP(e, Qa, Qb) + e  (registers only),
// then pred = relu(e_new@peW1c + Ra[s]+Rb[e] + pe_b1) . pe_w2 + pe_b2.
// ---------------------------------------------------------------------------
__global__ void __launch_bounds__(256, 3)
edge_en_pe(const float* __restrict__ e,
           const int* __restrict__ ip0, const int* __restrict__ ip1,
           const float* __restrict__ Qa, const float* __restrict__ Qb,
           const float* __restrict__ Ra, const float* __restrict__ Rb,
           const float* __restrict__ en_b1, const float* __restrict__ en_b2,
           const float* __restrict__ pe_b1v, const float* __restrict__ pe_b2v,
           const float* __restrict__ pe_w2v,
           float* __restrict__ pred, int nrows) {
    extern __shared__ char smem[];
    const uint32_t sb = smem_u32(smem);
    const int tid = threadIdx.x, lane = tid & 31, wid = tid >> 5;
    const int row0 = blockIdx.x * 64;
    const int g = lane >> 2, tig = lane & 3;
    const int m0 = (wid >> 1) * 16;
    const int nwn = (wid & 1) * 32;
    const int a_ro = (lane & 7) + ((lane >> 3) & 1) * 8;
    const int a_co = ((lane >> 4) & 1) * 8;
    const int b_ro = (lane & 7) + ((lane >> 4) & 1) * 8;
    const int b_co = ((lane >> 3) & 1) * 8;

    float* b1s = (float*)(smem + SM_B1);
    float* b2s = (float*)(smem + SM_B2);
    float* b1p = (float*)(smem + SM_B1P);
    float* w2s = (float*)(smem + SM_W2V);
    int*   s_ia = (int*)(smem + SM_IA);
    int*   s_ib = (int*)(smem + SM_IB);

    copyw_half(sb, tid, 10, 0);

    if (tid < 128) {
        b1s[tid] = en_b1[tid];
        b2s[tid] = en_b2[tid];
        b1p[tid] = pe_b1v[tid];
        w2s[tid] = pe_w2v[tid];
    }
    if (tid < 64) {
        int grow = row0 + tid;
        int ia = 0, ib = 0;
        if (grow < nrows) { ia = ip0[grow]; ib = ip1[grow]; }
        s_ia[tid] = ia; s_ib[tid] = ib;
        const char* qa = (const char*)(Qa + (size_t)ia * DD);
        const char* qb = (const char*)(Qb + (size_t)ib * DD);
        const char* ra = (const char*)(Ra + (size_t)ia * DD);
        const char* rb = (const char*)(Rb + (size_t)ib * DD);
        #pragma unroll
        for (int l = 0; l < 4; ++l) {
            asm volatile("prefetch.global.L2 [%0];" :: "l"(qa + l * 128));
            asm volatile("prefetch.global.L2 [%0];" :: "l"(qb + l * 128));
            asm volatile("prefetch.global.L2 [%0];" :: "l"(ra + l * 128));
            asm volatile("prefetch.global.L2 [%0];" :: "l"(rb + l * 128));
        }
    }

    float acc[2][4][4];
    zacc2(acc);

    stage_a<128>(smem, wid, lane, row0, e, nrows);
    layer_gemm_issued<8>(sb, tid, 10, m0, nwn, a_ro, a_co, b_ro, b_co, acc);
    pre_add(acc, Qa, Qb, s_ia, s_ib, row0, m0, nwn, g, tig, nrows);

    __syncthreads();
    copyw_half(sb, tid, 11, 0);
    acc_to_A(smem, acc, m0, nwn, g, tig, b1s, true);
    zacc2(acc);
    layer_gemm_issued<8>(sb, tid, 11, m0, nwn, a_ro, a_co, b_ro, b_co, acc);

    {
        const int rl = m0 + g;
        #pragma unroll
        for (int half = 0; half < 2; ++half) {
            int grow = row0 + rl + half * 8;
            if (grow < nrows) {
                #pragma unroll
                for (int p = 0; p < 2; ++p)
                    #pragma unroll
                    for (int na = 0; na < 4; ++na) {
                        int cc = p * 64 + nwn + na * 8 + 2 * tig;
                        float2 rv = *(const float2*)(e + (size_t)grow * DD + cc);
                        acc[p][na][half * 2 + 0] += b2s[cc] + rv.x;
                        acc[p][na][half * 2 + 1] += b2s[cc + 1] + rv.y;
                    }
            }
        }
    }

    __syncthreads();
    copyw_half(sb, tid, 14, 0);
    acc_to_A(smem, acc, m0, nwn, g, tig, nullptr, false);
    zacc2(acc);
    layer_gemm_issued<8>(sb, tid, 14, m0, nwn, a_ro, a_co, b_ro, b_co, acc);
    pre_add(acc, Ra, Rb, s_ia, s_ib, row0, m0, nwn, g, tig, nrows);

    float* hT = (float*)(smem + SM_AH);
    __syncthreads();
    {
        const int rl = m0 + g;
        #pragma unroll
        for (int p = 0; p < 2; ++p)
            #pragma unroll
            for (int na = 0; na < 4; ++na) {
                int cc = p * 64 + nwn + na * 8 + 2 * tig;
                hT[rl * 129 + cc]           = fmaxf(acc[p][na][0] + b1p[cc], 0.f);
                hT[rl * 129 + cc + 1]       = fmaxf(acc[p][na][1] + b1p[cc + 1], 0.f);
                hT[(rl + 8) * 129 + cc]     = fmaxf(acc[p][na][2] + b1p[cc], 0.f);
                hT[(rl + 8) * 129 + cc + 1] = fmaxf(acc[p][na][3] + b1p[cc + 1], 0.f);
            }
    }
    __syncthreads();
    if (tid < 64) {
        int grow = row0 + tid;
        float a = __ldg(&pe_b2v[0]);
        #pragma unroll 8
        for (int k = 0; k < 128; ++k) a += hT[tid * 129 + k] * w2s[k];
        if (grow < nrows) pred[grow] = a;
    }
}

// ---------------------------------------------------------------------------
extern "C" void kernel_launch(void* const* d_in, const int* in_sizes, int n_in,
                              void* d_out, int out_size) {
    const float* nodes = (const float*)d_in[0];
    const void*  eidx  = d_in[1];
    const float* ne_W1 = (const float*)d_in[2];
    const float* ne_b1 = (const float*)d_in[3];
    const float* ne_W2 = (const float*)d_in[4];
    const float* ne_b2 = (const float*)d_in[5];
    const float* ee_W1 = (const float*)d_in[6];
    const float* ee_b1 = (const float*)d_in[7];
    const float* ee_W2 = (const float*)d_in[8];
    const float* ee_b2 = (const float*)d_in[9];
    const float* nn_W1 = (const float*)d_in[10];
    const float* nn_b1 = (const float*)d_in[11];
    const float* nn_W2 = (const float*)d_in[12];
    const float* nn_b2 = (const float*)d_in[13];
    const float* en_W1 = (const float*)d_in[14];
    const float* en_b1 = (const float*)d_in[15];
    const float* en_W2 = (const float*)d_in[16];
    const float* en_b2 = (const float*)d_in[17];
    const float* pe_W1 = (const float*)d_in[18];
    const float* pe_b1 = (const float*)d_in[19];
    const float* pe_W2 = (const float*)d_in[20];
    const float* pe_b2 = (const float*)d_in[21];

    float *h, *h2, *m0, *m1, *e, *pa, *pb, *pc, *pd;
    int *st, *en_;
    __nv_bfloat16 *pwh, *pwl;
    cudaGetSymbolAddress((void**)&h,   g_h);
    cudaGetSymbolAddress((void**)&h2,  g_h2);
    cudaGetSymbolAddress((void**)&m0,  g_m0);
    cudaGetSymbolAddress((void**)&m1,  g_m1);
    cudaGetSymbolAddress((void**)&e,   g_e);
    cudaGetSymbolAddress((void**)&pa,  g_pa);
    cudaGetSymbolAddress((void**)&pb,  g_pb);
    cudaGetSymbolAddress((void**)&pc,  g_pc);
    cudaGetSymbolAddress((void**)&pd,  g_pd);
    cudaGetSymbolAddress((void**)&st,  g_start);
    cudaGetSymbolAddress((void**)&en_, g_end);
    cudaGetSymbolAddress((void**)&pwh, g_pwh);
    cudaGetSymbolAddress((void**)&pwl, g_pwl);

    cudaFuncSetAttribute(node_fused<1, 1, false, true, false>,
                         cudaFuncAttributeMaxDynamicSharedMemorySize, SM_TOTAL);
    cudaFuncSetAttribute(node_fused<2, 8, true, false, true>,
                         cudaFuncAttributeMaxDynamicSharedMemorySize, SM_TOTAL);
    cudaFuncSetAttribute(node_fused<2, 8, true, true, true>,
                         cudaFuncAttributeMaxDynamicSharedMemorySize, SM_TOTAL);
    cudaFuncSetAttribute(edge_mlp<0, true, false>,
                         cudaFuncAttributeMaxDynamicSharedMemorySize, SM_TOTAL);
    cudaFuncSetAttribute(edge_mlp<1, true, true>,
                         cudaFuncAttributeMaxDynamicSharedMemorySize, SM_TOTAL);
    cudaFuncSetAttribute(edge_en_pe,
                         cudaFuncAttributeMaxDynamicSharedMemorySize, SM_TOTAL);

    const int nblk_n = (N_NODES + 63) / 64;  // 1563
    const int nblk_e = (N_EDGES + 63) / 64;  // 9375

    convert_idx_kernel<<<(2 * N_EDGES + 255) / 256, 256>>>(eidx, st, en_, N_EDGES);
    pack_w_kernel<<<(15 * 16384 + 255) / 256, 256>>>(
        ne_W1, ne_W2, ee_W1, ee_W2, nn_W1, nn_W2, en_W1, en_W2, pe_W1, pwh, pwl);

    // h = MLP_ne(nodes);  Pa = h@eeW1a, Pb = h@eeW1b;  zero m0
    node_fused<1, 1, false, true, false><<<nblk_n, 256, SM_TOTAL>>>(
        nodes, nullptr, 0, 0, nullptr, nullptr, 0, 1,
        2, 3, pa, pb, ne_b1, ne_b2, nullptr, h, m0, N_NODES);

    // e = relu(Pa[s]+Pb[e]+b1)@eeW2 + b2;  scatter e -> m0
    edge_mlp<0, true, false><<<nblk_e, 256, SM_TOTAL>>>(
        nullptr, st, en_, pa, pb, 0, 4,
        ee_b1, ee_b2, nullptr, e, m0, N_EDGES);

    float* hA = h;
    float* hB = h2;
    float* msgs[2] = {m0, m1};

    for (int it = 0; it < NUM_ITERS; ++it) {
        float* mcur = msgs[it & 1];
        float* mnxt = msgs[(it + 1) & 1];
        const bool last = (it == NUM_ITERS - 1);
        float* zr = last ? nullptr : mnxt;

        if (!last) {
            node_fused<2, 8, true, false, true><<<nblk_n, 256, SM_TOTAL>>>(
                hA, mcur, 8, 9, pa, pb, 5, 7,
                0, 0, nullptr, nullptr, nn_b1, nn_b2, hA, hB, zr, N_NODES);

            edge_mlp<1, true, true><<<nblk_e, 256, SM_TOTAL>>>(
                e, st, en_, pa, pb, 10, 11,
                en_b1, en_b2, e, e, mnxt, N_EDGES);
        } else {
            node_fused<2, 8, true, true, true><<<nblk_n, 256, SM_TOTAL>>>(
                hA, mcur, 8, 9, pa, pb, 5, 7,
                12, 13, pc, pd, nn_b1, nn_b2, hA, hB, zr, N_NODES);

            edge_en_pe<<<nblk_e, 256, SM_TOTAL>>>(
                e, st, en_, pa, pb, pc, pd,
                en_b1, en_b2, pe_b1, pe_b2, pe_W2,
                (float*)d_out, N_EDGES);
        }

        float* t = hA; hA = hB; hB = t;
    }
}